// round 17
// baseline (speedup 1.0000x reference)
#include <cuda_runtime.h>
#include <cuda_fp16.h>
#include <cstdint>
#include <string.h>
#include <math.h>

// Problem constants
#define HIDDEN 2048
#define NHEADS 16
#define HDIM   128
#define SEQL   2048
#define BATCHN 2
#define WINDOW 256
#define ROWS   (BATCHN * SEQL)   // 4096
#define DM     (NHEADS * HDIM)   // 2048
#define KDIM   2048

// -------------------- scratch (no allocations allowed) --------------------
__device__ __half g_xh[ROWS * HIDDEN];
__device__ __half g_Wh[4 * KDIM * KDIM];
__device__ __half g_Qh[ROWS * DM];
__device__ __half g_Kh[ROWS * DM];
__device__ __half g_Vh[ROWS * DM];
__device__ __half g_ah[ROWS * DM];
__device__ float2 g_rope[SEQL * 64];       // (cos, sin) per (s, freq)

// ======================= PTX helpers =======================================
__device__ __forceinline__ uint32_t smem_u32(const void* p) {
    uint32_t a;
    asm("{ .reg .u64 t; cvta.to.shared.u64 t, %1; cvt.u32.u64 %0, t; }"
        : "=r"(a) : "l"(p));
    return a;
}
__device__ __forceinline__ uint32_t h2u(__half2 v) {
    uint32_t u;
    memcpy(&u, &v, 4);
    return u;
}
__device__ __forceinline__ void ldsm_x4(uint32_t& r0, uint32_t& r1,
                                        uint32_t& r2, uint32_t& r3, uint32_t a) {
    asm volatile("ldmatrix.sync.aligned.m8n8.x4.shared.b16 {%0,%1,%2,%3}, [%4];"
                 : "=r"(r0), "=r"(r1), "=r"(r2), "=r"(r3) : "r"(a));
}
__device__ __forceinline__ void ldsm_x4t(uint32_t& r0, uint32_t& r1,
                                         uint32_t& r2, uint32_t& r3, uint32_t a) {
    asm volatile("ldmatrix.sync.aligned.m8n8.x4.trans.shared.b16 {%0,%1,%2,%3}, [%4];"
                 : "=r"(r0), "=r"(r1), "=r"(r2), "=r"(r3) : "r"(a));
}
__device__ __forceinline__ void ldsm_x2(uint32_t& r0, uint32_t& r1, uint32_t a) {
    asm volatile("ldmatrix.sync.aligned.m8n8.x2.shared.b16 {%0,%1}, [%2];"
                 : "=r"(r0), "=r"(r1) : "r"(a));
}
__device__ __forceinline__ void mma16816h(float* d, const uint32_t* a,
                                          const uint32_t* b) {
    asm volatile(
        "mma.sync.aligned.m16n8k16.row.col.f32.f16.f16.f32 "
        "{%0,%1,%2,%3}, {%4,%5,%6,%7}, {%8,%9}, {%0,%1,%2,%3};"
        : "+f"(d[0]), "+f"(d[1]), "+f"(d[2]), "+f"(d[3])
        : "r"(a[0]), "r"(a[1]), "r"(a[2]), "r"(a[3]), "r"(b[0]), "r"(b[1]));
}
__device__ __forceinline__ void cpasync16(uint32_t dst, const void* src) {
    asm volatile("cp.async.cg.shared.global [%0], [%1], 16;"
                 :: "r"(dst), "l"(src));
}
#define CP_COMMIT() asm volatile("cp.async.commit_group;" ::: "memory")
#define CP_WAIT0()  asm volatile("cp.async.wait_group 0;" ::: "memory")
#define CP_WAIT2()  asm volatile("cp.async.wait_group 2;" ::: "memory")

// ===== prep: W -> fp16, x -> fp16, rope table (one launch) =================
struct WPtrs { const float* p[4]; };
#define WTOT (4u * KDIM * KDIM)            // 16777216
#define XTOT ((uint32_t)(ROWS * HIDDEN))   // 8388608
#define RTOT ((uint32_t)(SEQL * 64))       // 131072
#define ROPE_L2 0.2076205059304601f        // log2(10000)/64
__global__ void prep_kernel(WPtrs w, const float* __restrict__ x,
                            __half* __restrict__ wh, __half* __restrict__ xh,
                            float2* __restrict__ rope)
{
    size_t gid = (size_t)blockIdx.x * blockDim.x + threadIdx.x;
    if (gid < WTOT) {
        wh[gid] = __float2half(w.p[gid >> 22][gid & 0x3FFFFFu]);
    } else if (gid < WTOT + XTOT) {
        size_t i = gid - WTOT;
        xh[i] = __float2half(x[i]);
    } else if (gid < WTOT + XTOT + RTOT) {
        uint32_t i = (uint32_t)(gid - WTOT - XTOT);
        int s = i >> 6, f = i & 63;
        float inv = exp2f(-ROPE_L2 * (float)f);
        float c, sn;
        sincosf((float)s * inv, &c, &sn);
        rope[i] = make_float2(c, sn);
    }
}

// ====== fp16 GEMM: 512 thr, 16 warps (warp tile 32x32), 4-stage pipe =======
// CTA 128x128, K-chunk 32; grid.z = batch.
#define LDA 40
#define LDB 136
#define SZ_A (128 * LDA * 2)
#define SZ_B (32 * LDB * 2)
#define OFF_A   0
#define OFF_B   SZ_A
#define BUFSZ   (SZ_A + SZ_B)         // 18944 B
#define STAGES  4
#define GSMEM   (STAGES * BUFSZ)      // 75776 B

struct GemmBatch { const __half* B[3]; const float* bias[3]; void* C[3]; };

template <typename TOut>
__global__ __launch_bounds__(512) void gemm_mma_kernel(
    const __half* __restrict__ A, GemmBatch g)
{
    extern __shared__ __align__(16) char sm[];
    const uint32_t smb = smem_u32(sm);
    const __half* __restrict__ B    = g.B[blockIdx.z];
    const float*  __restrict__ bias = g.bias[blockIdx.z];
    TOut* __restrict__ C            = (TOut*)g.C[blockIdx.z];

    const int tid  = threadIdx.x;
    const int lane = tid & 31;
    const int wid  = tid >> 5;            // 0..15
    const int wm   = (wid >> 2) * 32;     // warp row (4 groups)
    const int wn   = (wid & 3) * 32;      // warp col (4 groups)
    const int m0   = blockIdx.y * 128;
    const int n0   = blockIdx.x * 128;

    // one cp.async per thread per tensor per stage
    const int am  = tid >> 2;             // 0..127
    const int ak  = (tid & 3) << 3;       // 0/8/16/24
    const int bk  = tid >> 4;             // 0..31
    const int bn  = (tid & 15) << 3;      // 0..120

    auto load_tile = [&](int it, int buf) {
        const int k0 = it * 32;
        const uint32_t base = smb + buf * BUFSZ;
        cpasync16(base + OFF_A + (uint32_t)(am * LDA + ak) * 2,
                  A + (size_t)(m0 + am) * KDIM + k0 + ak);
        cpasync16(base + OFF_B + (uint32_t)(bk * LDB + bn) * 2,
                  B + (size_t)(k0 + bk) * KDIM + n0 + bn);
        CP_COMMIT();
    };

    float acc[2][4][4];
    #pragma unroll
    for (int mi = 0; mi < 2; mi++)
        #pragma unroll
        for (int ni = 0; ni < 4; ni++)
            #pragma unroll
            for (int r = 0; r < 4; r++) acc[mi][ni][r] = 0.f;

    load_tile(0, 0);
    load_tile(1, 1);
    load_tile(2, 2);

    const int NIT = KDIM / 32;   // 64
    for (int it = 0; it < NIT; it++) {
        CP_WAIT2();
        __syncthreads();
        if (it + STAGES - 1 < NIT) load_tile(it + STAGES - 1, (it + STAGES - 1) & 3);

        const uint32_t base = smb + (it & 3) * BUFSZ;
        #pragma unroll
        for (int ks = 0; ks < 32; ks += 16) {
            uint32_t a[2][4], bb[2][4];
            #pragma unroll
            for (int mi = 0; mi < 2; mi++) {
                uint32_t adr = base + OFF_A +
                    (uint32_t)((wm + mi * 16 + (lane & 15)) * LDA +
                               ks + ((lane >> 4) << 3)) * 2;
                ldsm_x4(a[mi][0], a[mi][1], a[mi][2], a[mi][3], adr);
            }
            #pragma unroll
            for (int nj = 0; nj < 2; nj++) {
                uint32_t adr = base + OFF_B +
                    (uint32_t)((ks + (lane & 15)) * LDB + wn + nj * 16 +
                               ((lane >> 4) << 3)) * 2;
                ldsm_x4t(bb[nj][0], bb[nj][1], bb[nj][2], bb[nj][3], adr);
            }
            #pragma unroll
            for (int mi = 0; mi < 2; mi++)
                #pragma unroll
                for (int nj = 0; nj < 2; nj++) {
                    mma16816h(acc[mi][2 * nj],     a[mi], bb[nj]);
                    mma16816h(acc[mi][2 * nj + 1], a[mi], bb[nj] + 2);
                }
        }
    }

    const int r = lane >> 2;
    const int c = (lane & 3) << 1;
    #pragma unroll
    for (int mi = 0; mi < 2; mi++) {
        const int m1 = m0 + wm + mi * 16 + r;
        #pragma unroll
        for (int ni = 0; ni < 4; ni++) {
            const int n = n0 + wn + ni * 8 + c;
            float2 bb = *reinterpret_cast<const float2*>(bias + n);
            float v00 = acc[mi][ni][0] + bb.x, v01 = acc[mi][ni][1] + bb.y;
            float v10 = acc[mi][ni][2] + bb.x, v11 = acc[mi][ni][3] + bb.y;
            if constexpr (sizeof(TOut) == 2) {
                *reinterpret_cast<__half2*>(C + (size_t)m1 * KDIM + n) =
                    __floats2half2_rn(v00, v01);
                *reinterpret_cast<__half2*>(C + (size_t)(m1 + 8) * KDIM + n) =
                    __floats2half2_rn(v10, v11);
            } else {
                float2 o0 = {v00, v01}, o1 = {v10, v11};
                *reinterpret_cast<float2*>((float*)C + (size_t)m1 * KDIM + n)       = o0;
                *reinterpret_cast<float2*>((float*)C + (size_t)(m1 + 8) * KDIM + n) = o1;
            }
        }
    }
}

// ====== RoPE in-place on fp16 Q/K — table-driven (no MUFU) =================
__global__ __launch_bounds__(64) void rope_h_kernel(
    __half* __restrict__ Q, __half* __restrict__ K,
    const float2* __restrict__ tab)
{
    const int row = blockIdx.x;
    const int h   = blockIdx.y;
    const int i   = threadIdx.x;
    const int s   = row & (SEQL - 1);

    const float2 cs = tab[(s << 6) + i];
    const float c = cs.x, sn = cs.y;

    const size_t off = (size_t)row * DM + (size_t)h * HDIM + i;
    float q1 = __half2float(Q[off]), q2 = __half2float(Q[off + 64]);
    Q[off]      = __float2half( q1 * c + q2 * sn);
    Q[off + 64] = __float2half(-q1 * sn + q2 * c);
    float k1 = __half2float(K[off]), k2 = __half2float(K[off + 64]);
    K[off]      = __float2half( k1 * c + k2 * sn);
    K[off + 64] = __float2half(-k1 * sn + k2 * c);
}

// ========= MMA flash attention (fp16), double-buffered K/V tiles ===========
#define LDK 136
#define TILEB (64 * LDK * 2)
#define AOFF_Q 0
#define ASMEM  (5 * TILEB)            // 87040 B
#define LOG2E  1.4426950408889634f

__global__ __launch_bounds__(128) void swattn_mma_kernel(
    const __half* __restrict__ Qh, const __half* __restrict__ Kh,
    const __half* __restrict__ Vh, const float* __restrict__ kw,
    __half* __restrict__ Oh)
{
    extern __shared__ __align__(16) char sm[];
    const uint32_t smb = smem_u32(sm);
    const int tid  = threadIdx.x;
    const int lane = tid & 31;
    const int wid  = tid >> 5;
    const int bh   = blockIdx.y;
    const int b    = bh >> 4;
    const int h    = bh & 15;
    const int i0   = blockIdx.x * 64;
    const float scale2 = kw[h] * 0.08838834764831845f * LOG2E;

    const int g   = lane >> 2;
    const int tIG = lane & 3;
    const int rA  = i0 + wid * 16 + g;
    const int rB  = rA + 8;

    auto koff = [&](int buf) { return (uint32_t)(TILEB + buf * 2 * TILEB); };
    auto voff = [&](int buf) { return (uint32_t)(TILEB + buf * 2 * TILEB + TILEB); };

    auto load_kv = [&](int jt, int buf) {
        const __half* Kg = Kh + ((size_t)(b * SEQL + jt)) * DM + (size_t)h * HDIM;
        const __half* Vg = Vh + ((size_t)(b * SEQL + jt)) * DM + (size_t)h * HDIM;
        for (int idx = tid; idx < 64 * 16; idx += 128) {
            int r = idx >> 4, c = idx & 15;
            uint32_t d = (uint32_t)(r * LDK + c * 8) * 2;
            cpasync16(smb + koff(buf) + d, Kg + (size_t)r * DM + c * 8);
            cpasync16(smb + voff(buf) + d, Vg + (size_t)r * DM + c * 8);
        }
        CP_COMMIT();
    };

    int jt0 = i0 - WINDOW; if (jt0 < 0) jt0 = 0;
    {
        const __half* Qg = Qh + ((size_t)(b * SEQL + i0)) * DM + (size_t)h * HDIM;
        for (int idx = tid; idx < 64 * 16; idx += 128) {
            int r = idx >> 4, c = idx & 15;
            cpasync16(smb + AOFF_Q + (uint32_t)(r * LDK + c * 8) * 2,
                      Qg + (size_t)r * DM + c * 8);
        }
        load_kv(jt0, 0);
    }

    float oacc[16][4];
    #pragma unroll
    for (int nd = 0; nd < 16; nd++)
        #pragma unroll
        for (int r = 0; r < 4; r++) oacc[nd][r] = 0.f;
    float mA = -1e30f, mB = -1e30f, lsA = 0.f, lsB = 0.f;

    const int nt = (i0 - jt0) / 64 + 1;
    for (int n = 0; n < nt; n++) {
        const int jt  = jt0 + n * 64;
        const int buf = n & 1;
        CP_WAIT0();
        __syncthreads();
        if (n + 1 < nt) load_kv(jt + 64, buf ^ 1);

        float sacc[8][4];
        #pragma unroll
        for (int nj = 0; nj < 8; nj++)
            #pragma unroll
            for (int r = 0; r < 4; r++) sacc[nj][r] = 0.f;
        #pragma unroll
        for (int kt = 0; kt < 8; kt++) {
            uint32_t aq[4];
            {
                uint32_t adr = smb + AOFF_Q +
                    (uint32_t)((wid * 16 + (lane & 15)) * LDK +
                               kt * 16 + ((lane >> 4) << 3)) * 2;
                ldsm_x4(aq[0], aq[1], aq[2], aq[3], adr);
            }
            #pragma unroll
            for (int nj = 0; nj < 8; nj++) {
                uint32_t bfr[2];
                uint32_t adr = smb + koff(buf) +
                    (uint32_t)((nj * 8 + (lane & 7)) * LDK +
                               kt * 16 + (((lane >> 3) & 1) << 3)) * 2;
                ldsm_x2(bfr[0], bfr[1], adr);
                mma16816h(sacc[nj], aq, bfr);
            }
        }

        float p[8][4];
        #pragma unroll
        for (int nj = 0; nj < 8; nj++) {
            int j0 = jt + nj * 8 + 2 * tIG;
            int j1 = j0 + 1;
            p[nj][0] = (j0 <= rA && j0 >= rA - WINDOW) ? sacc[nj][0] * scale2 : -1e30f;
            p[nj][1] = (j1 <= rA && j1 >= rA - WINDOW) ? sacc[nj][1] * scale2 : -1e30f;
            p[nj][2] = (j0 <= rB && j0 >= rB - WINDOW) ? sacc[nj][2] * scale2 : -1e30f;
            p[nj][3] = (j1 <= rB && j1 >= rB - WINDOW) ? sacc[nj][3] * scale2 : -1e30f;
        }

        float tmA = -1e30f, tmB = -1e30f;
        #pragma unroll
        for (int nj = 0; nj < 8; nj++) {
            tmA = fmaxf(tmA, fmaxf(p[nj][0], p[nj][1]));
            tmB = fmaxf(tmB, fmaxf(p[nj][2], p[nj][3]));
        }
        #pragma unroll
        for (int off = 1; off <= 2; off <<= 1) {
            tmA = fmaxf(tmA, __shfl_xor_sync(0xffffffffu, tmA, off));
            tmB = fmaxf(tmB, __shfl_xor_sync(0xffffffffu, tmB, off));
        }
        float mnA = fmaxf(mA, tmA), mnB = fmaxf(mB, tmB);
        float alA = exp2f(mA - mnA), alB = exp2f(mB - mnB);

        float rsA = 0.f, rsB = 0.f;
        #pragma unroll
        for (int nj = 0; nj < 8; nj++) {
            p[nj][0] = exp2f(p[nj][0] - mnA);
            p[nj][1] = exp2f(p[nj][1] - mnA);
            p[nj][2] = exp2f(p[nj][2] - mnB);
            p[nj][3] = exp2f(p[nj][3] - mnB);
            rsA += p[nj][0] + p[nj][1];
            rsB += p[nj][2] + p[nj][3];
        }
        #pragma unroll
        for (int off = 1; off <= 2; off <<= 1) {
            rsA += __shfl_xor_sync(0xffffffffu, rsA, off);
            rsB += __shfl_xor_sync(0xffffffffu, rsB, off);
        }
        lsA = lsA * alA + rsA;
        lsB = lsB * alB + rsB;
        mA = mnA; mB = mnB;

        #pragma unroll
        for (int nd = 0; nd < 16; nd++) {
            oacc[nd][0] *= alA; oacc[nd][1] *= alA;
            oacc[nd][2] *= alB; oacc[nd][3] *= alB;
        }

        #pragma unroll
        for (int kk = 0; kk < 4; kk++) {
            uint32_t ap[4];
            ap[0] = h2u(__floats2half2_rn(p[2*kk][0],   p[2*kk][1]));
            ap[1] = h2u(__floats2half2_rn(p[2*kk][2],   p[2*kk][3]));
            ap[2] = h2u(__floats2half2_rn(p[2*kk+1][0], p[2*kk+1][1]));
            ap[3] = h2u(__floats2half2_rn(p[2*kk+1][2], p[2*kk+1][3]));
            #pragma unroll
            for (int nd = 0; nd < 8; nd++) {
                uint32_t bv[4];
                uint32_t adr = smb + voff(buf) +
                    (uint32_t)((kk * 16 + (lane & 15)) * LDK +
                               nd * 16 + ((lane >> 4) << 3)) * 2;
                ldsm_x4t(bv[0], bv[1], bv[2], bv[3], adr);
                mma16816h(oacc[2*nd],     ap, bv);
                mma16816h(oacc[2*nd + 1], ap, bv + 2);
            }
        }
    }

    const float ivA = 1.0f / lsA, ivB = 1.0f / lsB;
    __half* OgA = Oh + ((size_t)(b * SEQL + rA)) * DM + (size_t)h * HDIM;
    __half* OgB = Oh + ((size_t)(b * SEQL + rB)) * DM + (size_t)h * HDIM;
    #pragma unroll
    for (int nd = 0; nd < 16; nd++) {
        int col = nd * 8 + 2 * tIG;
        *reinterpret_cast<__half2*>(OgA + col) =
            __floats2half2_rn(oacc[nd][0] * ivA, oacc[nd][1] * ivA);
        *reinterpret_cast<__half2*>(OgB + col) =
            __floats2half2_rn(oacc[nd][2] * ivB, oacc[nd][3] * ivB);
    }
}

// =============================== launch ====================================
extern "C" void kernel_launch(void* const* d_in, const int* in_sizes, int n_in,
                              void* d_out, int out_size)
{
    const float* x = 0; const float* Ws[4] = {0,0,0,0};
    const float* bs[4] = {0,0,0,0}; const float* kww = 0;
    int nw = 0, nb = 0;
    for (int idx = 0; idx < n_in; idx++) {
        int sz = in_sizes[idx];
        const float* p = (const float*)d_in[idx];
        if      (sz == ROWS * HIDDEN) { if (!x) x = p; }
        else if (sz == HIDDEN * DM)   { if (nw < 4) Ws[nw++] = p; }
        else if (sz == DM)            { if (nb < 4) bs[nb++] = p; }
        else if (sz == NHEADS)        { if (!kww) kww = p; }
    }
    float* out = (float*)d_out;

    __half *xh, *wh, *qh, *kh, *vh, *ah;
    float2* rp;
    cudaGetSymbolAddress((void**)&xh, g_xh);
    cudaGetSymbolAddress((void**)&wh, g_Wh);
    cudaGetSymbolAddress((void**)&qh, g_Qh);
    cudaGetSymbolAddress((void**)&kh, g_Kh);
    cudaGetSymbolAddress((void**)&vh, g_Vh);
    cudaGetSymbolAddress((void**)&ah, g_ah);
    cudaGetSymbolAddress((void**)&rp, g_rope);

    cudaFuncSetAttribute(gemm_mma_kernel<__half>,
                         cudaFuncAttributeMaxDynamicSharedMemorySize, GSMEM);
    cudaFuncSetAttribute(gemm_mma_kernel<float>,
                         cudaFuncAttributeMaxDynamicSharedMemorySize, GSMEM);
    cudaFuncSetAttribute(swattn_mma_kernel,
                         cudaFuncAttributeMaxDynamicSharedMemorySize, ASMEM);

    // (1) conversions + rope table
    WPtrs wp; wp.p[0] = Ws[0]; wp.p[1] = Ws[1]; wp.p[2] = Ws[2]; wp.p[3] = Ws[3];
    prep_kernel<<<(WTOT + XTOT + RTOT) / 256, 256>>>(wp, x, wh, xh, rp);

    // (2) QKV fused, fp16 outputs
    GemmBatch gq;
    gq.B[0] = wh + 0 * (size_t)KDIM * KDIM; gq.bias[0] = bs[0]; gq.C[0] = qh;
    gq.B[1] = wh + 1 * (size_t)KDIM * KDIM; gq.bias[1] = bs[1]; gq.C[1] = kh;
    gq.B[2] = wh + 2 * (size_t)KDIM * KDIM; gq.bias[2] = bs[2]; gq.C[2] = vh;
    dim3 g3(KDIM / 128, ROWS / 128, 3);
    gemm_mma_kernel<__half><<<g3, 512, GSMEM>>>(xh, gq);

    // (3) rope in-place (table-driven)
    dim3 rgrid(ROWS, NHEADS);
    rope_h_kernel<<<rgrid, 64>>>(qh, kh, rp);

    // (4) MMA flash attention
    dim3 agrid(SEQL / 64, BATCHN * NHEADS);
    swattn_mma_kernel<<<agrid, 128, ASMEM>>>(qh, kh, vh, kww, ah);

    // (5) O projection, fp32 output
    GemmBatch go;
    go.B[0] = wh + 3 * (size_t)KDIM * KDIM; go.bias[0] = bs[3]; go.C[0] = out;
    go.B[1] = go.B[0]; go.bias[1] = bs[3]; go.C[1] = out;
    go.B[2] = go.B[0]; go.bias[2] = bs[3]; go.C[2] = out;
    dim3 g1(KDIM / 128, ROWS / 128, 1);
    gemm_mma_kernel<float><<<g1, 512, GSMEM>>>(ah, go);
}